// round 16
// baseline (speedup 1.0000x reference)
#include <cuda_runtime.h>
#include <cuda_fp16.h>
#include <math.h>
#include <stdint.h>

// ---------------- dims ----------------
#define Bsz 2
#define Tn  2048
#define Cn  1024
#define Vn  32000
#define Ln  4
#define En  3
#define Hn  4096
#define BT  (Bsz*Tn)
#define CH  16
#define CL  (Tn/CH)
#define KC  32

#define CC  (Cn*Cn)
#define WPL (32*CC)
#define WHEAD ((size_t)4*WPL)
#define WTOT  ((size_t)4*WPL + (size_t)Cn*Vn)

#define TILE_B 8192
#define STAGE_B (4*TILE_B)
#define SMEMB (3*STAGE_B)               // 96KB, 3-stage -> 2 CTAs/SM

// ---------------- scratch ----------------
__device__ float g_X  [BT*Cn];
__device__ float g_R  [BT*Cn];
__device__ float g_K  [BT*Cn];
__device__ float g_V  [BT*Cn];
__device__ float g_SC [BT];
__device__ float g_PART[Bsz*CH*Cn];
__device__ int   g_CNT[En];
__device__ int   g_LIST[En*BT];

__device__ __half g_MX1[BT*Cn], g_MX2[BT*Cn];           // mix, then rs
__device__ __half g_SP1[BT*Cn], g_SP2[BT*Cn];           // rwkv state pair
__device__ __half g_HB1[BT*Cn], g_HB2[BT*Cn];           // h pair
__device__ __half g_HD1[(size_t)BT*Hn], g_HD2[(size_t)BT*Hn];
__device__ __half g_WT1[WTOT], g_WT2[WTOT];

// ---------------- helpers ----------------
__device__ __forceinline__ void split2(float v, __half& h1, __half& h2) {
    h1 = __float2half_rn(v);
    float r = v - __half2float(h1);
    h2 = __float2half_rn(r);
}
__device__ __forceinline__ uint32_t smem_u32(const void* p) {
    uint32_t a;
    asm("{ .reg .u64 t; cvta.to.shared.u64 t, %1; cvt.u32.u64 %0, t; }" : "=r"(a) : "l"(p));
    return a;
}
#define CP16(dst, src) asm volatile("cp.async.cg.shared.global [%0], [%1], 16;" :: "r"(dst), "l"(src) : "memory")
#define CP_COMMIT()    asm volatile("cp.async.commit_group;" ::: "memory")
#define CP_WAIT1()     asm volatile("cp.async.wait_group 1;" ::: "memory")
#define CP_WAIT0()     asm volatile("cp.async.wait_group 0;" ::: "memory")
#define LDSM4(r, a) \
    asm volatile("ldmatrix.sync.aligned.m8n8.x4.shared.b16 {%0,%1,%2,%3}, [%4];" \
        : "=r"((r)[0]), "=r"((r)[1]), "=r"((r)[2]), "=r"((r)[3]) : "r"(a))
#define MMA16816(d, a, b0v, b1v) \
    asm volatile("mma.sync.aligned.m16n8k16.row.col.f32.f16.f16.f32 " \
        "{%0,%1,%2,%3}, {%4,%5,%6,%7}, {%8,%9}, {%0,%1,%2,%3};" \
        : "+f"((d)[0]), "+f"((d)[1]), "+f"((d)[2]), "+f"((d)[3]) \
        : "r"((a)[0]), "r"((a)[1]), "r"((a)[2]), "r"((a)[3]), "r"(b0v), "r"(b1v))
__device__ __forceinline__ uint32_t sw64(uint32_t o) { return o ^ ((o >> 2) & 0x30); }

// ---------------- GEMM core ----------------
// NP=3: {A1B1,A2B1,A1B2}   NP=2: {A1B1,A2B1}   NP=1: {A1B1} (pure fp16)
// 3-stage cp.async pipeline, ONE barrier per chunk. A source switches to (a1b,a2b)
// at k >= ksw (chunk-aligned). Pointers include row+half offsets.
template<int NP>
__device__ __forceinline__ void mma_core(
    uint32_t sbase,
    const __half* a1, const __half* a2, const __half* a1b, const __half* a2b, int ksw,
    const __half* b1, const __half* b2,
    int K, int tid, int lane, int wm, int wn, float acc[2][8][4])
{
    int arow = tid >> 1, half_ = tid & 1;
    uint32_t so[2];
#pragma unroll
    for (int q = 0; q < 2; q++)
        so[q] = sw64(arow*64 + half_*32 + q*16);

    // tile slots: 0=A1 1=A2 2=B1 3=B2
    const bool useT[4] = {true, NP >= 2, true, NP == 3};
    const int  nA = (NP >= 2) ? 2 : 1;
    int nc = K / KC;

    auto issue = [&](int c, uint32_t sb) {
        int k0 = c*KC;
        const __half* s0 = (k0 < ksw) ? a1 + k0 : a1b + (k0 - ksw);
        const __half* s1 = (k0 < ksw) ? a2 + k0 : a2b + (k0 - ksw);
        const __half* srcs[4] = {s0, s1, b1 + k0, b2 + k0};
#pragma unroll
        for (int t = 0; t < 4; t++) {
            if (!useT[t]) continue;
#pragma unroll
            for (int q = 0; q < 2; q++)
                CP16(sb + t*TILE_B + so[q], srcs[t] + q*8);
        }
        CP_COMMIT();
    };

    issue(0, sbase);
    if (nc > 1) issue(1, sbase + STAGE_B);

    for (int c = 0; c < nc; c++) {
        if (c + 1 < nc) CP_WAIT1();
        else            CP_WAIT0();
        __syncthreads();   // single barrier per chunk (3-stage makes trailing sync redundant)

        uint32_t stg = sbase + (uint32_t)(c % 3)*STAGE_B;
#pragma unroll
        for (int ks = 0; ks < 2; ks++) {
            // hoist A fragments for this k16-slab
            uint32_t afr[2][2][4];
#pragma unroll
            for (int as_ = 0; as_ < 2; as_++) {
                if (as_ >= nA) break;
#pragma unroll
                for (int mf = 0; mf < 2; mf++) {
                    uint32_t r  = wm*32 + mf*16 + (lane & 7) + ((lane & 8) ? 8 : 0);
                    uint32_t of = ks*32 + ((lane & 16) ? 16 : 0);
                    LDSM4(afr[as_][mf], stg + as_*TILE_B + sw64(r*64 + of));
                }
            }
            // B1 fragments; B frag mapping: row select lane&16, k-offset lane&8 (differs from A!)
            uint32_t bfr[4][4];
#pragma unroll
            for (int nq = 0; nq < 4; nq++) {
                uint32_t r  = wn*64 + nq*16 + (lane & 7) + ((lane & 16) ? 8 : 0);
                uint32_t of = ks*32 + ((lane & 8) ? 16 : 0);
                LDSM4(bfr[nq], stg + 2*TILE_B + sw64(r*64 + of));
            }
#pragma unroll
            for (int as_ = 0; as_ < 2; as_++) {
                if (as_ >= nA) break;
#pragma unroll
                for (int mf = 0; mf < 2; mf++)
#pragma unroll
                    for (int nf = 0; nf < 8; nf++)
                        MMA16816(acc[mf][nf], afr[as_][mf], bfr[nf>>1][(nf&1)*2], bfr[nf>>1][(nf&1)*2 + 1]);
            }
            if (NP == 3) {
                // B2 fragments, A1*B2
#pragma unroll
                for (int nq = 0; nq < 4; nq++) {
                    uint32_t r  = wn*64 + nq*16 + (lane & 7) + ((lane & 16) ? 8 : 0);
                    uint32_t of = ks*32 + ((lane & 8) ? 16 : 0);
                    LDSM4(bfr[nq], stg + 3*TILE_B + sw64(r*64 + of));
                }
#pragma unroll
                for (int mf = 0; mf < 2; mf++)
#pragma unroll
                    for (int nf = 0; nf < 8; nf++)
                        MMA16816(acc[mf][nf], afr[0][mf], bfr[nf>>1][(nf&1)*2], bfr[nf>>1][(nf&1)*2 + 1]);
            }
        }
        if (c + 2 < nc) issue(c + 2, sbase + (uint32_t)((c + 2) % 3)*STAGE_B);
    }
}

#define MMA_PROLOG() \
    extern __shared__ char smem[]; \
    uint32_t sbase = smem_u32(smem); \
    int tid = threadIdx.x, lane = tid & 31, wid = tid >> 5; \
    int wm = wid & 3, wn = wid >> 2; \
    int arow = tid >> 1, half_ = tid & 1; \
    float acc[2][8][4]; \
    _Pragma("unroll") for (int i = 0; i < 2; i++) \
    _Pragma("unroll") for (int j = 0; j < 8; j++) \
    _Pragma("unroll") for (int q = 0; q < 4; q++) acc[i][j][q] = 0.f;

// ---------------- fused r/k/v GEMM: grid(24, 32) ----------------
__global__ void __launch_bounds__(256, 2) rkv_mma(
    const __half* __restrict__ A1, const __half* __restrict__ A2,
    const __half* __restrict__ B1, const __half* __restrict__ B2)
{
    MMA_PROLOG();
    int m0 = blockIdx.y * 128;
    size_t aro = (size_t)(m0 + arow)*Cn + half_*16;
    size_t bro = (size_t)(blockIdx.x*128 + arow)*Cn + half_*16;
    mma_core<3>(sbase, A1 + aro, A2 + aro, A1 + aro, A2 + aro, Cn,
                B1 + bro, B2 + bro, Cn, tid, lane, wm, wn, acc);

    int mat = blockIdx.x >> 3;
    float* outp = (mat == 0) ? g_R : ((mat == 1) ? g_K : g_V);
    int cbase = (blockIdx.x & 7)*128 + wn*64;
#pragma unroll
    for (int mf = 0; mf < 2; mf++) {
        int r0 = m0 + wm*32 + mf*16 + (lane >> 2);
#pragma unroll
        for (int nf = 0; nf < 8; nf++) {
            int cc = cbase + nf*8 + (lane & 3)*2;
#pragma unroll
            for (int h = 0; h < 2; h++) {
                int r = r0 + h*8;
                float v0 = acc[mf][nf][h*2], v1 = acc[mf][nf][h*2 + 1];
                if (mat == 0) {
                    v0 = 1.f/(1.f + expf(-v0));
                    v1 = 1.f/(1.f + expf(-v1));
                }
                float* cr = outp + (size_t)r*Cn + cc;
                cr[0] = v0; cr[1] = v1;
            }
        }
    }
}

// ---------------- generic dense GEMM: MODE 0: C=acc  2: C+=acc ----------------
// SWAP: m-tile on blockIdx.x (fastest) so wave-mates share B tiles (head: keeps A
// L2-resident, B streamed once). STREAM: st.global.cs epilogue (don't pollute L2).
template<int MODE, int NP, bool SWAP, bool STREAM>
__global__ void __launch_bounds__(256, 2) gemm_mma(
    const __half* __restrict__ A1, const __half* __restrict__ A2,
    const __half* __restrict__ B1, const __half* __restrict__ B2,
    float* __restrict__ Cf, int K, int N)
{
    MMA_PROLOG();
    int mi = SWAP ? blockIdx.x : blockIdx.y;
    int ni = SWAP ? blockIdx.y : blockIdx.x;
    int m0 = mi * 128;
    size_t aro = (size_t)(m0 + arow)*K + half_*16;
    size_t bro = (size_t)(ni*128 + arow)*K + half_*16;
    mma_core<NP>(sbase, A1 + aro, A2 + aro, A1 + aro, A2 + aro, K,
                 B1 + bro, B2 + bro, K, tid, lane, wm, wn, acc);

    int cbase = ni*128 + wn*64;
#pragma unroll
    for (int mf = 0; mf < 2; mf++) {
        int r0 = m0 + wm*32 + mf*16 + (lane >> 2);
#pragma unroll
        for (int nf = 0; nf < 8; nf++) {
            int cc = cbase + nf*8 + (lane & 3)*2;
#pragma unroll
            for (int h = 0; h < 2; h++) {
                int r = r0 + h*8;
                float v0 = acc[mf][nf][h*2], v1 = acc[mf][nf][h*2 + 1];
                float* cr = Cf + (size_t)r*N + cc;
                if (MODE == 2) { cr[0] += v0; cr[1] += v1; }
                else if (STREAM) { __stcs(cr, v0); __stcs(cr + 1, v1); }
                else           { cr[0] = v0;  cr[1] = v1; }
            }
        }
    }
}

// ---------------- fused expert up-proj: grid(32, 32, 3); A row stride Cn, switch at ksw=Cn
struct UpArgs {
    const __half* A1[3]; const __half* A2[3];
    const __half* A1b[3]; const __half* A2b[3];
    const __half* B1[3]; const __half* B2[3];
    int K[3];
};
template<int NP>
__global__ void __launch_bounds__(256, 2) up3_mma(UpArgs ua) {
    int z = blockIdx.z;
    int Meff = g_CNT[z];
    int m0 = blockIdx.y * 128;
    if (m0 >= Meff) return;
    const int* rows = g_LIST + z*BT;
    int K = ua.K[z];

    MMA_PROLOG();
    int am = m0 + arow;
    int amc = (am < Meff) ? am : (Meff - 1);
    size_t aro = (size_t)rows[amc]*Cn + half_*16;
    size_t bro = (size_t)(blockIdx.x*128 + arow)*K + half_*16;
    mma_core<NP>(sbase, ua.A1[z] + aro, ua.A2[z] + aro, ua.A1b[z] + aro, ua.A2b[z] + aro, Cn,
                 ua.B1[z] + bro, ua.B2[z] + bro, K, tid, lane, wm, wn, acc);

    int cbase = blockIdx.x*128 + wn*64;
#pragma unroll
    for (int mf = 0; mf < 2; mf++) {
        int r0 = m0 + wm*32 + mf*16 + (lane >> 2);
#pragma unroll
        for (int nf = 0; nf < 8; nf++) {
            int cc = cbase + nf*8 + (lane & 3)*2;
#pragma unroll
            for (int h = 0; h < 2; h++) {
                int r = r0 + h*8;
                if (r >= Meff) continue;
                size_t o = (size_t)rows[r]*Hn + cc;
                float v0 = fmaxf(acc[mf][nf][h*2],     0.f);
                float v1 = fmaxf(acc[mf][nf][h*2 + 1], 0.f);
                split2(v0, g_HD1[o],   g_HD2[o]);
                split2(v1, g_HD1[o+1], g_HD2[o+1]);
            }
        }
    }
}

// ---------------- fused expert down-proj: grid(8, 32, 3) ----------------
struct DnArgs { const __half* B1[3]; const __half* B2[3]; };
template<int NP>
__global__ void __launch_bounds__(256, 2) dn3_mma(DnArgs da) {
    int z = blockIdx.z;
    int Meff = g_CNT[z];
    int m0 = blockIdx.y * 128;
    if (m0 >= Meff) return;
    const int* rows = g_LIST + z*BT;

    MMA_PROLOG();
    int am = m0 + arow;
    int amc = (am < Meff) ? am : (Meff - 1);
    size_t aro = (size_t)rows[amc]*Hn + half_*16;
    size_t bro = (size_t)(blockIdx.x*128 + arow)*Hn + half_*16;
    mma_core<NP>(sbase, g_HD1 + aro, g_HD2 + aro, g_HD1 + aro, g_HD2 + aro, Hn,
                 da.B1[z] + bro, da.B2[z] + bro, Hn, tid, lane, wm, wn, acc);

    int cbase = blockIdx.x*128 + wn*64;
#pragma unroll
    for (int mf = 0; mf < 2; mf++) {
        int r0 = m0 + wm*32 + mf*16 + (lane >> 2);
#pragma unroll
        for (int nf = 0; nf < 8; nf++) {
            int cc = cbase + nf*8 + (lane & 3)*2;
#pragma unroll
            for (int h = 0; h < 2; h++) {
                int r = r0 + h*8;
                if (r >= Meff) continue;
                int tok = rows[r];
                float sc = g_SC[tok];
                float* xr = g_X + (size_t)tok*Cn + cc;
                xr[0] += acc[mf][nf][h*2]*sc;
                xr[1] += acc[mf][nf][h*2 + 1]*sc;
            }
        }
    }
}

// ---------------- embedding gather ----------------
__global__ void embed_k(const int* __restrict__ idx, const float* __restrict__ emb) {
    int i = blockIdx.x*blockDim.x + threadIdx.x;
    if (i >= BT*Cn) return;
    int row = i >> 10, c = i & 1023;
    g_X[i] = emb[(size_t)idx[row]*Cn + c];
}

// ---------------- fused ln1 + token-shift mix -> MX pair ----------------
__global__ void ln1mix_k(const float* __restrict__ in, const float* __restrict__ g,
                         const float* __restrict__ b) {
    int row = blockIdx.x;
    int t = row & (Tn - 1);
    const float* p = in + (size_t)row*Cn;
    const float* pp = in + (size_t)(row-1)*Cn;
    float v[4], u[4];
    float s = 0.f, ss = 0.f, su = 0.f, ssu = 0.f;
#pragma unroll
    for (int j = 0; j < 4; j++) {
        int c = threadIdx.x + j*256;
        v[j] = p[c];
        s += v[j]; ss += v[j]*v[j];
        u[j] = (t > 0) ? pp[c] : 0.f;
        su += u[j]; ssu += u[j]*u[j];
    }
#pragma unroll
    for (int o = 16; o > 0; o >>= 1) {
        s   += __shfl_xor_sync(0xffffffffu, s,   o);
        ss  += __shfl_xor_sync(0xffffffffu, ss,  o);
        su  += __shfl_xor_sync(0xffffffffu, su,  o);
        ssu += __shfl_xor_sync(0xffffffffu, ssu, o);
    }
    __shared__ float sh[4][8];
    int w = threadIdx.x >> 5;
    if ((threadIdx.x & 31) == 0) { sh[0][w] = s; sh[1][w] = ss; sh[2][w] = su; sh[3][w] = ssu; }
    __syncthreads();
    s = 0.f; ss = 0.f; su = 0.f; ssu = 0.f;
#pragma unroll
    for (int j = 0; j < 8; j++) { s += sh[0][j]; ss += sh[1][j]; su += sh[2][j]; ssu += sh[3][j]; }
    float mv = s*(1.f/Cn),  rv = rsqrtf(ss*(1.f/Cn) - mv*mv + 1e-5f);
    float mu = su*(1.f/Cn), ru = rsqrtf(ssu*(1.f/Cn) - mu*mu + 1e-5f);
#pragma unroll
    for (int j = 0; j < 4; j++) {
        int c = threadIdx.x + j*256;
        float hv = (v[j]-mv)*rv*g[c] + b[c];
        float hu = (t > 0) ? ((u[j]-mu)*ru*g[c] + b[c]) : 0.f;
        float mix = 0.5f*(hv + hu);
        size_t id = (size_t)row*Cn + c;
        split2(mix, g_MX1[id], g_MX2[id]);
    }
}

// ---------------- fused ln2 + route (or plain lnf) -> HB pair ----------------
template<bool ROUTE>
__global__ void ln2r_k(const float* __restrict__ in, const float* __restrict__ g,
                       const float* __restrict__ b,
                       __half* __restrict__ o1, __half* __restrict__ o2,
                       const float* __restrict__ wc, const float* __restrict__ wa,
                       const float* __restrict__ shp) {
    int row = blockIdx.x;
    const float* p = in + (size_t)row*Cn;
    float v[4];
    float s = 0.f, ss = 0.f;
#pragma unroll
    for (int j = 0; j < 4; j++) {
        v[j] = p[threadIdx.x + j*256];
        s += v[j]; ss += v[j]*v[j];
    }
#pragma unroll
    for (int o = 16; o > 0; o >>= 1) {
        s  += __shfl_xor_sync(0xffffffffu, s,  o);
        ss += __shfl_xor_sync(0xffffffffu, ss, o);
    }
    __shared__ float sh[2][8];
    int w = threadIdx.x >> 5;
    if ((threadIdx.x & 31) == 0) { sh[0][w] = s; sh[1][w] = ss; }
    __syncthreads();
    s = 0.f; ss = 0.f;
#pragma unroll
    for (int j = 0; j < 8; j++) { s += sh[0][j]; ss += sh[1][j]; }
    float mean = s * (1.f/Cn);
    float rstd = rsqrtf(ss*(1.f/Cn) - mean*mean + 1e-5f);

    float pq[6] = {0,0,0,0,0,0};
#pragma unroll
    for (int j = 0; j < 4; j++) {
        int c = threadIdx.x + j*256;
        float val = (v[j]-mean)*rstd*g[c] + b[c];
        size_t id = (size_t)row*Cn + c;
        split2(val, o1[id], o2[id]);
        if (ROUTE) {
            pq[0] += val*wc[c];
            pq[1] += val*wc[Cn + c];
            pq[2] += val*wc[2*Cn + c];
            pq[3] += val*wa[c*En + 0];
            pq[4] += val*wa[c*En + 1];
            pq[5] += val*wa[c*En + 2];
        }
    }
    if (ROUTE) {
#pragma unroll
        for (int o = 16; o > 0; o >>= 1)
#pragma unroll
            for (int q = 0; q < 6; q++) pq[q] += __shfl_xor_sync(0xffffffffu, pq[q], o);
        __shared__ float sm[8][6];
        if ((threadIdx.x & 31) == 0)
#pragma unroll
            for (int q = 0; q < 6; q++) sm[w][q] = pq[q];
        __syncthreads();
        if (threadIdx.x == 0) {
            float d[6];
#pragma unroll
            for (int q = 0; q < 6; q++) {
                d[q] = 0.f;
#pragma unroll
                for (int ww = 0; ww < 8; ww++) d[q] += sm[ww][q];
            }
            float best = -3.4e38f, wcf = 0.f;
            int wi = 0;
#pragma unroll
            for (int e = 0; e < En; e++) {
                float conf = 1.f/(1.f + expf(-d[e]));
                float bid  = conf*shp[e] + d[3+e];
                if (bid > best) { best = bid; wi = e; wcf = conf; }
            }
            g_SC[row] = wcf / (wcf + 1e-6f);
            int pos = atomicAdd(&g_CNT[wi], 1);
            g_LIST[wi*BT + pos] = row;
        }
    }
}

// ---------------- scan phase 1 (+ CNT zeroing for this layer's routing) ----------------
__global__ void scan1_k() {
    if (blockIdx.x == 0 && threadIdx.x < En) g_CNT[threadIdx.x] = 0;
    int i = blockIdx.x*blockDim.x + threadIdx.x;
    if (i >= Bsz*CH*Cn) return;
    int c  = i & 1023;
    int ch = (i >> 10) & (CH - 1);
    int b  = i >> 14;
    size_t base = (size_t)b*Tn*Cn + (size_t)ch*CL*Cn + c;
    float s = 0.f;
#pragma unroll 4
    for (int t = 0; t < CL; t++) {
        size_t id = base + (size_t)t*Cn;
        s += g_K[id]*g_V[id];
    }
    g_PART[i] = s;
}
// ---------------- scan phase 2+3 fused ----------------
__global__ void scan3_k() {
    int i = blockIdx.x*blockDim.x + threadIdx.x;
    if (i >= Bsz*CH*Cn) return;
    int c  = i & 1023;
    int ch = (i >> 10) & (CH - 1);
    int b  = i >> 14;
    float acc = 0.f;
    for (int j = 0; j < CH; j++)
        if (j < ch) acc += g_PART[((b*CH + j) << 10) | c];
    size_t base = (size_t)b*Tn*Cn + (size_t)ch*CL*Cn + c;
    int t0 = ch*CL;
#pragma unroll 4
    for (int t = 0; t < CL; t++) {
        size_t id = base + (size_t)t*Cn;
        acc += g_K[id]*g_V[id];
        float st = acc / (float)(t0 + t + 1);
        split2(st, g_SP1[id], g_SP2[id]);
        float rs = g_R[id]*st;
        split2(rs, g_MX1[id], g_MX2[id]);
    }
}

// ---------------- batched weight transpose+split ----------------
__global__ void tsplit_k(const float* __restrict__ W,
                         __half* __restrict__ o1, __half* __restrict__ o2,
                         int K, int N, size_t srcStride, size_t dstStride) {
    __shared__ __half s1[32][33], s2[32][33];
    int z = blockIdx.z;
    W  += (size_t)z*srcStride;
    o1 += (size_t)z*dstStride;
    o2 += (size_t)z*dstStride;
    int n0 = blockIdx.x*32, k0 = blockIdx.y*32;
    int tx = threadIdx.x, ty = threadIdx.y;
#pragma unroll
    for (int j = 0; j < 4; j++) {
        int k = k0 + ty + j*8;
        float v = W[(size_t)k*N + n0 + tx];
        split2(v, s1[ty+j*8][tx], s2[ty+j*8][tx]);
    }
    __syncthreads();
#pragma unroll
    for (int j = 0; j < 4; j++) {
        int n = n0 + ty + j*8;
        size_t o = (size_t)n*K + k0 + tx;
        o1[o] = s1[tx][ty+j*8];
        o2[o] = s2[tx][ty+j*8];
    }
}

// ---------------- launch ----------------
extern "C" void kernel_launch(void* const* d_in, const int* in_sizes, int n_in,
                              void* d_out, int out_size)
{
    const int*   idx   = (const int*)  d_in[0];
    const float* shares= (const float*)d_in[1];
    const float* emb   = (const float*)d_in[2];
    const float* ln1g  = (const float*)d_in[3];
    const float* ln1b  = (const float*)d_in[4];
    const float* ln2g  = (const float*)d_in[5];
    const float* ln2b  = (const float*)d_in[6];
    const float* Wr    = (const float*)d_in[7];
    const float* Wk    = (const float*)d_in[8];
    const float* Wv    = (const float*)d_in[9];
    const float* Wo    = (const float*)d_in[10];
    const float* W1    = (const float*)d_in[11];
    const float* W2    = (const float*)d_in[12];
    const float* wconf = (const float*)d_in[13];
    const float* Wl1   = (const float*)d_in[14];
    const float* Wl2   = (const float*)d_in[15];
    const float* Waff  = (const float*)d_in[17];
    const float* lnfg  = (const float*)d_in[18];
    const float* lnfb  = (const float*)d_in[19];
    const float* headW = (const float*)d_in[20];
    float* out = (float*)d_out;
    (void)in_sizes; (void)n_in; (void)out_size;

    float *X;
    __half *MX1,*MX2, *SP1,*SP2, *HB1,*HB2, *WT1,*WT2;
    cudaGetSymbolAddress((void**)&X,   g_X);
    cudaGetSymbolAddress((void**)&MX1, g_MX1); cudaGetSymbolAddress((void**)&MX2, g_MX2);
    cudaGetSymbolAddress((void**)&SP1, g_SP1); cudaGetSymbolAddress((void**)&SP2, g_SP2);
    cudaGetSymbolAddress((void**)&HB1, g_HB1); cudaGetSymbolAddress((void**)&HB2, g_HB2);
    cudaGetSymbolAddress((void**)&WT1, g_WT1); cudaGetSymbolAddress((void**)&WT2, g_WT2);

    cudaFuncSetAttribute(rkv_mma,                      cudaFuncAttributeMaxDynamicSharedMemorySize, SMEMB);
    cudaFuncSetAttribute(gemm_mma<2,3,false,false>,    cudaFuncAttributeMaxDynamicSharedMemorySize, SMEMB);
    cudaFuncSetAttribute(gemm_mma<0,1,true,true>,      cudaFuncAttributeMaxDynamicSharedMemorySize, SMEMB);
    cudaFuncSetAttribute(up3_mma<3>,                   cudaFuncAttributeMaxDynamicSharedMemorySize, SMEMB);
    cudaFuncSetAttribute(up3_mma<2>,                   cudaFuncAttributeMaxDynamicSharedMemorySize, SMEMB);
    cudaFuncSetAttribute(dn3_mma<3>,                   cudaFuncAttributeMaxDynamicSharedMemorySize, SMEMB);
    cudaFuncSetAttribute(dn3_mma<2>,                   cudaFuncAttributeMaxDynamicSharedMemorySize, SMEMB);

    dim3 tb(32, 8);
    // arena per layer: Wr@0 Wk@CC Wv@2CC Wo@3CC | W1e0@4CC W1e1@8CC | W2e0@12CC W2e1@16CC | Wl1@20CC Wl2@28CC
    tsplit_k<<<dim3(Cn/32, Cn/32, Ln), tb>>>(Wr, WT1,              WT2,              Cn, Cn, CC, WPL);
    tsplit_k<<<dim3(Cn/32, Cn/32, Ln), tb>>>(Wk, WT1+CC,           WT2+CC,           Cn, Cn, CC, WPL);
    tsplit_k<<<dim3(Cn/32, Cn/32, Ln), tb>>>(Wv, WT1+2*(size_t)CC, WT2+2*(size_t)CC, Cn, Cn, CC, WPL);
    tsplit_k<<<dim3(Cn/32, Cn/32, Ln), tb>>>(Wo, WT1+3*(size_t)CC, WT2+3*(size_t)CC, Cn, Cn, CC, WPL);
    tsplit_k<<<dim3(Hn/32, Cn/32, Ln), tb>>>(W1,                 WT1+4*(size_t)CC,  WT2+4*(size_t)CC,  Cn, Hn, 2*(size_t)Cn*Hn, WPL);
    tsplit_k<<<dim3(Hn/32, Cn/32, Ln), tb>>>(W1 + (size_t)Cn*Hn, WT1+8*(size_t)CC,  WT2+8*(size_t)CC,  Cn, Hn, 2*(size_t)Cn*Hn, WPL);
    tsplit_k<<<dim3(Cn/32, Hn/32, Ln), tb>>>(W2,                 WT1+12*(size_t)CC, WT2+12*(size_t)CC, Hn, Cn, 2*(size_t)Hn*Cn, WPL);
    tsplit_k<<<dim3(Cn/32, Hn/32, Ln), tb>>>(W2 + (size_t)Hn*Cn, WT1+16*(size_t)CC, WT2+16*(size_t)CC, Hn, Cn, 2*(size_t)Hn*Cn, WPL);
    tsplit_k<<<dim3(Hn/32, 2*Cn/32, Ln), tb>>>(Wl1, WT1+20*(size_t)CC, WT2+20*(size_t)CC, 2*Cn, Hn, 2*(size_t)Cn*Hn, WPL);
    tsplit_k<<<dim3(Cn/32, Hn/32, Ln), tb>>>(Wl2, WT1+28*(size_t)CC, WT2+28*(size_t)CC, Hn, Cn, (size_t)Hn*Cn, WPL);
    tsplit_k<<<dim3(Vn/32, Cn/32, 1), tb>>>(headW, WT1+WHEAD, WT2+WHEAD, Cn, Vn, 0, 0);

    embed_k<<<(BT*Cn)/256, 256>>>(idx, emb);

    for (int l = 0; l < Ln; l++) {
        size_t LB = (size_t)l*WPL;
        ln1mix_k<<<BT, 256>>>(X, ln1g + (size_t)l*Cn, ln1b + (size_t)l*Cn);

        rkv_mma<<<dim3(24, 32), 256, SMEMB>>>(MX1, MX2, WT1+LB, WT2+LB);

        scan1_k<<<(Bsz*CH*Cn)/256, 256>>>();   // also zeroes CNT for this layer
        scan3_k<<<(Bsz*CH*Cn)/256, 256>>>();

        gemm_mma<2,3,false,false><<<dim3(8, 32), 256, SMEMB>>>(MX1, MX2, WT1+LB+3*(size_t)CC, WT2+LB+3*(size_t)CC, X, Cn, Cn);

        ln2r_k<true><<<BT, 256>>>(X, ln2g + (size_t)l*Cn, ln2b + (size_t)l*Cn, HB1, HB2,
                                  wconf + (size_t)l*En*Cn, Waff + (size_t)l*Cn*En,
                                  shares + (size_t)l*En);

        UpArgs ua;
        DnArgs da;
        for (int e = 0; e < 2; e++) {
            size_t o1 = LB + (4 + 4*e)*(size_t)CC;
            size_t o2 = LB + (12 + 4*e)*(size_t)CC;
            ua.A1[e] = HB1; ua.A2[e] = HB2;
            ua.A1b[e] = HB1; ua.A2b[e] = HB2;   // unused (K=Cn)
            ua.B1[e] = WT1 + o1; ua.B2[e] = WT2 + o1;
            ua.K[e] = Cn;
            da.B1[e] = WT1 + o2; da.B2[e] = WT2 + o2;
        }
        ua.A1[2] = HB1; ua.A2[2] = HB2;
        ua.A1b[2] = SP1; ua.A2b[2] = SP2;       // second half of hz = state pair
        ua.B1[2] = WT1 + LB + 20*(size_t)CC; ua.B2[2] = WT2 + LB + 20*(size_t)CC;
        ua.K[2] = 2*Cn;
        da.B1[2] = WT1 + LB + 28*(size_t)CC; da.B2[2] = WT2 + LB + 28*(size_t)CC;

        if (l == Ln - 1) {
            // last layer: expert outputs feed only lnf/head (no further routing) ->
            // 2-product suffices (error class validated at ~2e-4 on logits)
            up3_mma<2><<<dim3(32, 32, 3), 256, SMEMB>>>(ua);
            dn3_mma<2><<<dim3(8, 32, 3), 256, SMEMB>>>(da);
        } else {
            up3_mma<3><<<dim3(32, 32, 3), 256, SMEMB>>>(ua);
            dn3_mma<3><<<dim3(8, 32, 3), 256, SMEMB>>>(da);
        }
    }

    ln2r_k<false><<<BT, 256>>>(X, lnfg, lnfb, HB1, HB2, nullptr, nullptr, nullptr);
    // head: pure fp16 single product; SWAP grid (m fastest) keeps A L2-resident and
    // lets wave-mates share B tiles; streaming stores keep logits out of L2.
    gemm_mma<0,1,true,true><<<dim3(BT/128, Vn/128), 256, SMEMB>>>(HB1, HB2, WT1+WHEAD, WT2+WHEAD, out, Cn, Vn);
}